// round 1
// baseline (speedup 1.0000x reference)
#include <cuda_runtime.h>
#include <cstdint>
#include <cstdio>

#define BB  8
#define NP  2048
#define KNN 20
#define NEG_INF (-3.4e38f)

// ---------------- scratch (static device globals; no allocation) ----------------
__device__ float g_xc[(size_t)BB * 512 * NP];          // concat of x1..x4 (channels 0..511)
__device__ float g_y [(size_t)BB * 256 * NP];
__device__ float g_z [(size_t)BB * 256 * NP];
__device__ float g_sq[BB * NP];
__device__ int   g_idx[BB * NP * KNN];
__device__ float g_dist[(size_t)BB * NP * NP];         // 134 MB
__device__ float g_hm[BB * 1024];
__device__ float g_h1[BB * 512];
__device__ float g_h2[BB * 256];

// ---------------- kernels ----------------

__global__ void zero_k(float* p, int n) {
    int t = blockIdx.x * 256 + threadIdx.x;
    if (t < n) p[t] = 0.f;
}

__global__ void sqnorm_k(const float* __restrict__ x, size_t xbs, int C,
                         float* __restrict__ sq) {
    int t = blockIdx.x * 256 + threadIdx.x;
    if (t >= BB * NP) return;
    int b = t / NP, n = t % NP;
    const float* xp = x + (size_t)b * xbs + n;
    float s = 0.f;
    for (int c = 0; c < C; c++) { float v = xp[(size_t)c * NP]; s = fmaf(v, v, s); }
    sq[t] = s;
}

// dist[b,n,m] = 2*sum_c x[c,n]x[c,m] - sq[n] - sq[m]   (64x64 tile, K-chunk 16)
__global__ __launch_bounds__(256) void dist_k(const float* __restrict__ x, size_t xbs, int C,
                                              const float* __restrict__ sq,
                                              float* __restrict__ dist) {
    int b = blockIdx.z, n0 = blockIdx.y * 64, m0 = blockIdx.x * 64;
    __shared__ float As[16][65];
    __shared__ float Bs[16][65];
    int tid = threadIdx.x;
    int tx = tid & 15, ty = tid >> 4;
    const float* xb = x + (size_t)b * xbs;
    float acc[4][4];
#pragma unroll
    for (int i = 0; i < 4; i++)
#pragma unroll
        for (int j = 0; j < 4; j++) acc[i][j] = 0.f;

    for (int c0 = 0; c0 < C; c0 += 16) {
#pragma unroll
        for (int t = 0; t < 4; t++) {
            int e = tid + t * 256;
            int cc = e >> 6, nn = e & 63;
            As[cc][nn] = (c0 + cc < C) ? xb[(size_t)(c0 + cc) * NP + n0 + nn] : 0.f;
            Bs[cc][nn] = (c0 + cc < C) ? xb[(size_t)(c0 + cc) * NP + m0 + nn] : 0.f;
        }
        __syncthreads();
#pragma unroll
        for (int kk = 0; kk < 16; kk++) {
            float ar[4], br[4];
#pragma unroll
            for (int i = 0; i < 4; i++) ar[i] = As[kk][ty + 16 * i];
#pragma unroll
            for (int j = 0; j < 4; j++) br[j] = Bs[kk][tx + 16 * j];
#pragma unroll
            for (int i = 0; i < 4; i++)
#pragma unroll
                for (int j = 0; j < 4; j++) acc[i][j] = fmaf(ar[i], br[j], acc[i][j]);
        }
        __syncthreads();
    }
    float sm[4], sn[4];
#pragma unroll
    for (int j = 0; j < 4; j++) sm[j] = sq[b * NP + m0 + tx + 16 * j];
#pragma unroll
    for (int i = 0; i < 4; i++) sn[i] = sq[b * NP + n0 + ty + 16 * i];
#pragma unroll
    for (int i = 0; i < 4; i++) {
        int n = n0 + ty + 16 * i;
#pragma unroll
        for (int j = 0; j < 4; j++) {
            int m = m0 + tx + 16 * j;
            dist[(size_t)b * NP * NP + (size_t)n * NP + m] = 2.f * acc[i][j] - sn[i] - sm[j];
        }
    }
}

// per-row top-K (set semantics: order irrelevant, consumed by max over k)
__global__ __launch_bounds__(256) void topk_k(const float* __restrict__ dist,
                                              int* __restrict__ idxout) {
    int r = blockIdx.x;                 // b*NP + n
    __shared__ float sv[NP];
    __shared__ float rv[8];
    __shared__ int   ri[8];
    const float* row = dist + (size_t)r * NP;
    for (int i = threadIdx.x; i < NP; i += 256) sv[i] = row[i];
    __syncthreads();
    int lane = threadIdx.x & 31, wid = threadIdx.x >> 5;
    for (int it = 0; it < KNN; it++) {
        float best = NEG_INF;
        int bi = threadIdx.x;
        for (int i = threadIdx.x; i < NP; i += 256) {
            float v = sv[i];
            if (v > best) { best = v; bi = i; }
        }
#pragma unroll
        for (int off = 16; off > 0; off >>= 1) {
            float ov = __shfl_down_sync(0xffffffffu, best, off);
            int   oi = __shfl_down_sync(0xffffffffu, bi, off);
            if (ov > best || (ov == best && oi < bi)) { best = ov; bi = oi; }
        }
        if (lane == 0) { rv[wid] = best; ri[wid] = bi; }
        __syncthreads();
        if (threadIdx.x == 0) {
            float bv = rv[0]; int bj = ri[0];
            for (int w = 1; w < 8; w++)
                if (rv[w] > bv || (rv[w] == bv && ri[w] < bj)) { bv = rv[w]; bj = ri[w]; }
            idxout[(size_t)r * KNN + it] = bj;
            sv[bj] = NEG_INF;
        }
        __syncthreads();
    }
}

// out[b,o,n] = sum_c Weff[o,c] * X[b,c,n]
// wmode 0: Weff = W[o*ldw+c]; wmode 1: Weff = W[o*ldw+C+c] - W[o*ldw+c]
// ep 0: plain store to out[b,o,n]
// ep 1: v=relu(g[o]*rs*acc+bb[o]); atomicMax over n into out[b*O+o] (int bits, v>=0)
__global__ __launch_bounds__(256) void gemm_k(const float* __restrict__ X, size_t xbs, int C,
                                              const float* __restrict__ W, int ldw, int wmode,
                                              int O, float* __restrict__ out,
                                              const float* __restrict__ g,
                                              const float* __restrict__ bb, int ep) {
    int b = blockIdx.z, o0 = blockIdx.y * 64, n0 = blockIdx.x * 64;
    __shared__ float Ws[16][65];
    __shared__ float Xs[16][65];
    int tid = threadIdx.x;
    int tx = tid & 15, ty = tid >> 4;
    const float* xb = X + (size_t)b * xbs;
    float acc[4][4];
#pragma unroll
    for (int i = 0; i < 4; i++)
#pragma unroll
        for (int j = 0; j < 4; j++) acc[i][j] = 0.f;

    for (int c0 = 0; c0 < C; c0 += 16) {
#pragma unroll
        for (int t = 0; t < 4; t++) {
            int e = tid + t * 256;
            { // W tile: o_l = e>>4, kk = e&15
                int ol = e >> 4, kk = e & 15;
                int c = c0 + kk;
                float wv = 0.f;
                if (c < C) {
                    const float* wr = W + (size_t)(o0 + ol) * ldw;
                    wv = (wmode == 0) ? wr[c] : (wr[C + c] - wr[c]);
                }
                Ws[kk][ol] = wv;
            }
            { // X tile: cc = e>>6, nn = e&63
                int cc = e >> 6, nn = e & 63;
                Xs[cc][nn] = (c0 + cc < C) ? xb[(size_t)(c0 + cc) * NP + n0 + nn] : 0.f;
            }
        }
        __syncthreads();
#pragma unroll
        for (int kk = 0; kk < 16; kk++) {
            float wr[4], xr[4];
#pragma unroll
            for (int i = 0; i < 4; i++) wr[i] = Ws[kk][ty + 16 * i];
#pragma unroll
            for (int j = 0; j < 4; j++) xr[j] = Xs[kk][tx + 16 * j];
#pragma unroll
            for (int i = 0; i < 4; i++)
#pragma unroll
                for (int j = 0; j < 4; j++) acc[i][j] = fmaf(wr[i], xr[j], acc[i][j]);
        }
        __syncthreads();
    }

    if (ep == 0) {
#pragma unroll
        for (int i = 0; i < 4; i++) {
            int o = o0 + ty + 16 * i;
#pragma unroll
            for (int j = 0; j < 4; j++) {
                int n = n0 + tx + 16 * j;
                out[((size_t)b * O + o) * NP + n] = acc[i][j];
            }
        }
    } else {
        float rs = rsqrtf(1.f + 1e-5f);
#pragma unroll
        for (int i = 0; i < 4; i++) {
            int o = o0 + ty + 16 * i;
            float gn = g[o] * rs, bo = bb[o];
            float m = NEG_INF;
#pragma unroll
            for (int j = 0; j < 4; j++) {
                float v = fmaxf(fmaf(gn, acc[i][j], bo), 0.f);
                m = fmaxf(m, v);
            }
            atomicMax((int*)out + (size_t)b * O + o, __float_as_int(m));
        }
    }
}

// out[b,o,n] = relu(gn[o]*(max_k y[b,o,idx[b,n,k]] + z[b,o,n]) + bb[o])
__global__ __launch_bounds__(256) void gathermax_k(const float* __restrict__ y,
                                                   const float* __restrict__ z,
                                                   const int* __restrict__ idx,
                                                   const float* __restrict__ g,
                                                   const float* __restrict__ bb,
                                                   int O, float* __restrict__ out, size_t obs) {
    int b = blockIdx.z, n0 = blockIdx.y * 64, o0 = blockIdx.x * 4;
    __shared__ int sidx[64 * KNN];
    for (int e = threadIdx.x; e < 64 * KNN; e += 256) {
        int nl = e / KNN, kk = e % KNN;
        sidx[e] = idx[((size_t)(b * NP + n0 + nl)) * KNN + kk];
    }
    __syncthreads();
    int nl = threadIdx.x & 63, ol = threadIdx.x >> 6;
    int o = o0 + ol, n = n0 + nl;
    const float* yp = y + ((size_t)b * O + o) * NP;
    float m = NEG_INF;
#pragma unroll
    for (int kk = 0; kk < KNN; kk++) m = fmaxf(m, yp[sidx[nl * KNN + kk]]);
    float v = m + z[((size_t)b * O + o) * NP + n];
    float rs = rsqrtf(1.f + 1e-5f);
    v = fmaxf(fmaf(g[o] * rs, v, bb[o]), 0.f);
    out[(size_t)b * obs + (size_t)o * NP + n] = v;
}

// fully-connected: out[b,j] = (relu(bn(...)))? of sum_c in[b,c]*W[j,c]
__global__ void fc_k(const float* __restrict__ in, int CI, const float* __restrict__ W,
                     int CO, const float* __restrict__ g, const float* __restrict__ bb,
                     float* __restrict__ out, int act) {
    int t = blockIdx.x * 256 + threadIdx.x;
    if (t >= BB * CO) return;
    int b = t / CO, j = t % CO;
    const float* ip = in + (size_t)b * CI;
    const float* wp = W + (size_t)j * CI;
    float s = 0.f;
    for (int c = 0; c < CI; c++) s = fmaf(ip[c], wp[c], s);
    if (act) {
        float rs = rsqrtf(1.f + 1e-5f);
        s = fmaxf(fmaf(g[j] * rs, s, bb[j]), 0.f);
    }
    out[t] = s;
}

// ---------------- host side ----------------

static void edge_conv_launch(const float* xin, size_t xbs, int C,
                             const float* W, int ldw, int O,
                             const float* g, const float* bbp,
                             float* xcOut,
                             float* y, float* z, float* sq, float* dist, int* idxp) {
    sqnorm_k<<<(BB * NP + 255) / 256, 256>>>(xin, xbs, C, sq);
    dist_k<<<dim3(NP / 64, NP / 64, BB), 256>>>(xin, xbs, C, sq, dist);
    topk_k<<<BB * NP, 256>>>(dist, idxp);
    gemm_k<<<dim3(NP / 64, O / 64, BB), 256>>>(xin, xbs, C, W, ldw, 0, O, y, nullptr, nullptr, 0);
    gemm_k<<<dim3(NP / 64, O / 64, BB), 256>>>(xin, xbs, C, W, ldw, 1, O, z, nullptr, nullptr, 0);
    gathermax_k<<<dim3(O / 4, NP / 64, BB), 256>>>(y, z, idxp, g, bbp, O, xcOut, (size_t)512 * NP);
}

extern "C" void kernel_launch(void* const* d_in, const int* in_sizes, int n_in,
                              void* d_out, int out_size) {
    const float* x   = (const float*)d_in[0];
    const float* w1  = (const float*)d_in[1];
    const float* w2  = (const float*)d_in[2];
    const float* w3  = (const float*)d_in[3];
    const float* w4  = (const float*)d_in[4];
    const float* w5  = (const float*)d_in[5];
    const float* fw1 = (const float*)d_in[6];
    const float* fw2 = (const float*)d_in[7];
    const float* fw3 = (const float*)d_in[8];
    const float* g1 = (const float*)d_in[9],  *b1 = (const float*)d_in[10];
    const float* g2 = (const float*)d_in[11], *b2 = (const float*)d_in[12];
    const float* g3 = (const float*)d_in[13], *b3 = (const float*)d_in[14];
    const float* g4 = (const float*)d_in[15], *b4 = (const float*)d_in[16];
    const float* g5 = (const float*)d_in[17], *b5 = (const float*)d_in[18];
    const float* g6 = (const float*)d_in[19], *b6 = (const float*)d_in[20];
    const float* g7 = (const float*)d_in[21], *b7 = (const float*)d_in[22];
    // d_in[23] is k (==20, compiled in)

    float *xc, *y, *z, *sq, *dist, *hm, *h1, *h2;
    int* idxp;
    cudaGetSymbolAddress((void**)&xc,   g_xc);
    cudaGetSymbolAddress((void**)&y,    g_y);
    cudaGetSymbolAddress((void**)&z,    g_z);
    cudaGetSymbolAddress((void**)&sq,   g_sq);
    cudaGetSymbolAddress((void**)&dist, g_dist);
    cudaGetSymbolAddress((void**)&hm,   g_hm);
    cudaGetSymbolAddress((void**)&h1,   g_h1);
    cudaGetSymbolAddress((void**)&h2,   g_h2);
    cudaGetSymbolAddress((void**)&idxp, g_idx);

    zero_k<<<(BB * 1024 + 255) / 256, 256>>>(hm, BB * 1024);

    // edge convs; outputs written straight into the concat buffer g_xc
    edge_conv_launch(x,                        (size_t)3 * NP,   3,   w1, 6,   64,  g1, b1,
                     xc + (size_t)0 * NP,   y, z, sq, dist, idxp);
    edge_conv_launch(xc,                       (size_t)512 * NP, 64,  w2, 128, 64,  g2, b2,
                     xc + (size_t)64 * NP,  y, z, sq, dist, idxp);
    edge_conv_launch(xc + (size_t)64 * NP,     (size_t)512 * NP, 64,  w3, 128, 128, g3, b3,
                     xc + (size_t)128 * NP, y, z, sq, dist, idxp);
    edge_conv_launch(xc + (size_t)128 * NP,    (size_t)512 * NP, 128, w4, 256, 256, g4, b4,
                     xc + (size_t)256 * NP, y, z, sq, dist, idxp);

    // conv5 (1024x512) fused with bn+relu+max_n via int-bit atomicMax epilogue
    gemm_k<<<dim3(NP / 64, 1024 / 64, BB), 256>>>(xc, (size_t)512 * NP, 512, w5, 512, 0,
                                                  1024, hm, g5, b5, 1);

    // FC head
    fc_k<<<(BB * 512 + 255) / 256, 256>>>(hm, 1024, fw1, 512, g6, b6, h1, 1);
    fc_k<<<(BB * 256 + 255) / 256, 256>>>(h1, 512, fw2, 256, g7, b7, h2, 1);
    fc_k<<<(BB * 40 + 255) / 256, 256>>>(h2, 256, fw3, 40, nullptr, nullptr, (float*)d_out, 0);
}

// round 2
// speedup vs baseline: 1.3488x; 1.3488x over previous
#include <cuda_runtime.h>
#include <cstdint>
#include <cstdio>

#define BB  8
#define NP  2048
#define KNN 20
#define NEG_INF (-3.4e38f)

// ---------------- scratch (static device globals; no allocation) ----------------
__device__ float g_xc[(size_t)BB * 512 * NP];          // concat of x1..x4
__device__ float g_y [(size_t)BB * 256 * NP];
__device__ float g_z [(size_t)BB * 256 * NP];
__device__ float g_sq[BB * NP];
__device__ int   g_idx[BB * NP * KNN];
__device__ float g_dist[(size_t)BB * NP * NP];         // 134 MB
__device__ float g_hm[BB * 1024];
__device__ float g_h1[BB * 512];
__device__ float g_h2[BB * 256];

// ---------------- small kernels ----------------

__global__ void zero_k(float* p, int n) {
    int t = blockIdx.x * 256 + threadIdx.x;
    if (t < n) p[t] = 0.f;
}

__global__ void sqnorm_k(const float* __restrict__ x, size_t xbs, int C,
                         float* __restrict__ sq) {
    int t = blockIdx.x * 256 + threadIdx.x;
    if (t >= BB * NP) return;
    int b = t / NP, n = t % NP;
    const float* xp = x + (size_t)b * xbs + n;
    float s = 0.f;
    for (int c = 0; c < C; c++) { float v = xp[(size_t)c * NP]; s = fmaf(v, v, s); }
    sq[t] = s;
}

// ---------------- dist: symmetric 128x128-tile GEMM, 8x8 micro ----------------
// dist[b,n,m] = 2*sum_c x[c,n]x[c,m] - sq[n] - sq[m]; only upper-tri tiles computed.
__global__ __launch_bounds__(256) void dist2_k(const float* __restrict__ x, size_t xbs, int C,
                                               const float* __restrict__ sq,
                                               float* __restrict__ dist) {
    int b = blockIdx.z;
    int t = blockIdx.x;                       // triangular tile index, i <= j
    int j = (int)((sqrtf(8.f * t + 1.f) - 1.f) * 0.5f);
    while ((j + 1) * (j + 2) / 2 <= t) j++;
    while (j * (j + 1) / 2 > t) j--;
    int i = t - j * (j + 1) / 2;
    int n0 = i * 128, m0 = j * 128;

    __shared__ float As[16][128];
    __shared__ float Bs[16][128];
    int tid = threadIdx.x, tx = tid & 15, ty = tid >> 4;
    const float* xb = x + (size_t)b * xbs;

    float acc[8][8];
#pragma unroll
    for (int r = 0; r < 8; r++)
#pragma unroll
        for (int c = 0; c < 8; c++) acc[r][c] = 0.f;

    for (int c0 = 0; c0 < C; c0 += 16) {
#pragma unroll
        for (int q = 0; q < 2; q++) {
            int e = tid + q * 256;
            int rr = e >> 5, c4 = (e & 31) * 4;
            float4 va = make_float4(0.f, 0.f, 0.f, 0.f);
            float4 vb = make_float4(0.f, 0.f, 0.f, 0.f);
            if (c0 + rr < C) {
                va = *(const float4*)&xb[(size_t)(c0 + rr) * NP + n0 + c4];
                vb = *(const float4*)&xb[(size_t)(c0 + rr) * NP + m0 + c4];
            }
            *(float4*)&As[rr][c4] = va;
            *(float4*)&Bs[rr][c4] = vb;
        }
        __syncthreads();
#pragma unroll
        for (int kk = 0; kk < 16; kk++) {
            float a[8], bv[8];
            *(float4*)(a)      = *(const float4*)&As[kk][ty * 8];
            *(float4*)(a + 4)  = *(const float4*)&As[kk][ty * 8 + 4];
            *(float4*)(bv)     = *(const float4*)&Bs[kk][tx * 8];
            *(float4*)(bv + 4) = *(const float4*)&Bs[kk][tx * 8 + 4];
#pragma unroll
            for (int r = 0; r < 8; r++)
#pragma unroll
                for (int c = 0; c < 8; c++) acc[r][c] = fmaf(a[r], bv[c], acc[r][c]);
        }
        __syncthreads();
    }

    float sn[8], sm[8];
#pragma unroll
    for (int r = 0; r < 8; r++) sn[r] = sq[b * NP + n0 + ty * 8 + r];
#pragma unroll
    for (int c = 0; c < 8; c++) sm[c] = sq[b * NP + m0 + tx * 8 + c];
#pragma unroll
    for (int r = 0; r < 8; r++)
#pragma unroll
        for (int c = 0; c < 8; c++) acc[r][c] = 2.f * acc[r][c] - sn[r] - sm[c];

    float* dbase = dist + (size_t)b * NP * NP;
#pragma unroll
    for (int r = 0; r < 8; r++) {
        float* p = &dbase[(size_t)(n0 + ty * 8 + r) * NP + m0 + tx * 8];
        *(float4*)p       = *(float4*)&acc[r][0];
        *(float4*)(p + 4) = *(float4*)&acc[r][4];
    }
    if (i != j) {
#pragma unroll
        for (int c = 0; c < 8; c++) {
            float4 lo = make_float4(acc[0][c], acc[1][c], acc[2][c], acc[3][c]);
            float4 hi = make_float4(acc[4][c], acc[5][c], acc[6][c], acc[7][c]);
            float* p = &dbase[(size_t)(m0 + tx * 8 + c) * NP + n0 + ty * 8];
            *(float4*)p       = lo;
            *(float4*)(p + 4) = hi;
        }
    }
}

// ---------------- top-K: register-resident two-phase REDUX pop ----------------
__global__ __launch_bounds__(256) void topk2_k(const float* __restrict__ dist,
                                               int* __restrict__ idxout) {
    int r = blockIdx.x;                        // b*NP + n
    const float* row = dist + (size_t)r * NP;
    unsigned u[8];
#pragma unroll
    for (int q = 0; q < 8; q++) {
        unsigned bt = __float_as_uint(row[threadIdx.x + 256 * q]);
        u[q] = (bt & 0x80000000u) ? ~bt : (bt | 0x80000000u);   // monotonic map
    }
    __shared__ unsigned cv[8 * KNN];
    __shared__ int      ci[8 * KNN];
    int lane = threadIdx.x & 31, w = threadIdx.x >> 5;

    // phase 1: each warp pops its own top-20 of its 256 values (no block syncs)
#pragma unroll 1
    for (int it = 0; it < KNN; it++) {
        unsigned best = u[0]; int bs = 0;
#pragma unroll
        for (int q = 1; q < 8; q++) if (u[q] > best) { best = u[q]; bs = q; }
        unsigned wm = __reduce_max_sync(0xffffffffu, best);
        unsigned bal = __ballot_sync(0xffffffffu, best == wm);
        if (lane == (int)(__ffs(bal) - 1)) {
            cv[w * KNN + it] = wm;
            ci[w * KNN + it] = threadIdx.x + (bs << 8);
#pragma unroll
            for (int q = 0; q < 8; q++) if (q == bs) u[q] = 0u;
        }
    }
    __syncthreads();

    // phase 2: warp 0 merges 160 candidates -> global top-20
    if (w == 0) {
        unsigned c5[5];
#pragma unroll
        for (int q = 0; q < 5; q++) c5[q] = cv[lane * 5 + q];
#pragma unroll 1
        for (int it = 0; it < KNN; it++) {
            unsigned best = c5[0]; int bs = 0;
#pragma unroll
            for (int q = 1; q < 5; q++) if (c5[q] > best) { best = c5[q]; bs = q; }
            unsigned wm = __reduce_max_sync(0xffffffffu, best);
            unsigned bal = __ballot_sync(0xffffffffu, best == wm);
            if (lane == (int)(__ffs(bal) - 1)) {
                idxout[(size_t)r * KNN + it] = ci[lane * 5 + bs];
#pragma unroll
                for (int q = 0; q < 5; q++) if (q == bs) c5[q] = 0u;
            }
        }
    }
}

// ---------------- W x X GEMM: MTx128 tile, (MT/16)x8 micro ----------------
// out[b,o,n] = sum_c Weff[o,c] * X[b,c,n]
// wmode 0: Weff=W[o*ldw+c]; 1: Weff=W[o*ldw+C+c]-W[o*ldw+c]
// ep 0: plain store; ep 1: relu(bn) + atomicMax over n into out[b*O+o]
template <int MT>
__global__ __launch_bounds__(256) void mm_k(const float* __restrict__ X, size_t xbs, int C,
                                            const float* __restrict__ W, int ldw, int wmode,
                                            int O, float* __restrict__ out,
                                            const float* __restrict__ g,
                                            const float* __restrict__ bb, int ep) {
    constexpr int MR = MT / 16;
    int b = blockIdx.z, o0 = blockIdx.y * MT, n0 = blockIdx.x * 128;
    __shared__ float Ws[16][MT + 1];
    __shared__ float Xs[16][128];
    int tid = threadIdx.x, tx = tid & 15, ty = tid >> 4;
    const float* xb = X + (size_t)b * xbs;

    float acc[MR][8];
#pragma unroll
    for (int r = 0; r < MR; r++)
#pragma unroll
        for (int c = 0; c < 8; c++) acc[r][c] = 0.f;

    for (int c0 = 0; c0 < C; c0 += 16) {
#pragma unroll
        for (int q = 0; q < MT / 16; q++) {
            int e = tid + q * 256;
            int kk = e & 15, ol = e >> 4;
            int c = c0 + kk;
            float wv = 0.f;
            if (c < C) {
                const float* wr = W + (size_t)(o0 + ol) * ldw;
                wv = wmode ? (wr[C + c] - wr[c]) : wr[c];
            }
            Ws[kk][ol] = wv;
        }
#pragma unroll
        for (int q = 0; q < 2; q++) {
            int e = tid + q * 256;
            int rr = e >> 5, c4 = (e & 31) * 4;
            float4 v = make_float4(0.f, 0.f, 0.f, 0.f);
            if (c0 + rr < C) v = *(const float4*)&xb[(size_t)(c0 + rr) * NP + n0 + c4];
            *(float4*)&Xs[rr][c4] = v;
        }
        __syncthreads();
#pragma unroll
        for (int kk = 0; kk < 16; kk++) {
            float a[MR], bv[8];
#pragma unroll
            for (int r = 0; r < MR; r++) a[r] = Ws[kk][ty * MR + r];
            *(float4*)(bv)     = *(const float4*)&Xs[kk][tx * 8];
            *(float4*)(bv + 4) = *(const float4*)&Xs[kk][tx * 8 + 4];
#pragma unroll
            for (int r = 0; r < MR; r++)
#pragma unroll
                for (int c = 0; c < 8; c++) acc[r][c] = fmaf(a[r], bv[c], acc[r][c]);
        }
        __syncthreads();
    }

    if (ep == 0) {
#pragma unroll
        for (int r = 0; r < MR; r++) {
            int o = o0 + ty * MR + r;
            float* p = &out[((size_t)b * O + o) * NP + n0 + tx * 8];
            *(float4*)p       = *(float4*)&acc[r][0];
            *(float4*)(p + 4) = *(float4*)&acc[r][4];
        }
    } else {
        float rs = rsqrtf(1.f + 1e-5f);
#pragma unroll
        for (int r = 0; r < MR; r++) {
            int o = o0 + ty * MR + r;
            float gn = g[o] * rs, bo = bb[o];
            float m = 0.f;
#pragma unroll
            for (int c = 0; c < 8; c++) {
                float v = fmaxf(fmaf(gn, acc[r][c], bo), 0.f);
                m = fmaxf(m, v);
            }
            atomicMax((int*)out + (size_t)b * O + o, __float_as_int(m));
        }
    }
}

// ---------------- gather + max_k + bn + relu ----------------
__global__ __launch_bounds__(256) void gathermax_k(const float* __restrict__ y,
                                                   const float* __restrict__ z,
                                                   const int* __restrict__ idx,
                                                   const float* __restrict__ g,
                                                   const float* __restrict__ bb,
                                                   int O, float* __restrict__ out, size_t obs) {
    int b = blockIdx.z, n0 = blockIdx.y * 64, o0 = blockIdx.x * 4;
    __shared__ int sidx[64 * KNN];
    for (int e = threadIdx.x; e < 64 * KNN; e += 256) {
        int nl = e / KNN, kk = e % KNN;
        sidx[e] = idx[((size_t)(b * NP + n0 + nl)) * KNN + kk];
    }
    __syncthreads();
    int nl = threadIdx.x & 63, ol = threadIdx.x >> 6;
    int o = o0 + ol, n = n0 + nl;
    const float* yp = y + ((size_t)b * O + o) * NP;
    float m = NEG_INF;
#pragma unroll
    for (int kk = 0; kk < KNN; kk++) m = fmaxf(m, yp[sidx[nl * KNN + kk]]);
    float v = m + z[((size_t)b * O + o) * NP + n];
    float rs = rsqrtf(1.f + 1e-5f);
    v = fmaxf(fmaf(g[o] * rs, v, bb[o]), 0.f);
    out[(size_t)b * obs + (size_t)o * NP + n] = v;
}

// ---------------- FC head ----------------
__global__ void fc_k(const float* __restrict__ in, int CI, const float* __restrict__ W,
                     int CO, const float* __restrict__ g, const float* __restrict__ bb,
                     float* __restrict__ out, int act) {
    int t = blockIdx.x * 256 + threadIdx.x;
    if (t >= BB * CO) return;
    int b = t / CO, j = t % CO;
    const float4* ip = (const float4*)(in + (size_t)b * CI);
    const float4* wp = (const float4*)(W + (size_t)j * CI);
    float s = 0.f;
    for (int c = 0; c < CI / 4; c++) {
        float4 a = ip[c], w = wp[c];
        s = fmaf(a.x, w.x, s); s = fmaf(a.y, w.y, s);
        s = fmaf(a.z, w.z, s); s = fmaf(a.w, w.w, s);
    }
    if (act) {
        float rs = rsqrtf(1.f + 1e-5f);
        s = fmaxf(fmaf(g[j] * rs, s, bb[j]), 0.f);
    }
    out[t] = s;
}

// ---------------- host side ----------------

static void edge_conv_launch(const float* xin, size_t xbs, int C,
                             const float* W, int ldw, int O,
                             const float* g, const float* bbp,
                             float* xcOut,
                             float* y, float* z, float* sq, float* dist, int* idxp) {
    sqnorm_k<<<(BB * NP + 255) / 256, 256>>>(xin, xbs, C, sq);
    dist2_k<<<dim3(136, 1, BB), 256>>>(xin, xbs, C, sq, dist);
    topk2_k<<<BB * NP, 256>>>(dist, idxp);
    if (O >= 128) {
        mm_k<128><<<dim3(NP / 128, O / 128, BB), 256>>>(xin, xbs, C, W, ldw, 0, O, y, nullptr, nullptr, 0);
        mm_k<128><<<dim3(NP / 128, O / 128, BB), 256>>>(xin, xbs, C, W, ldw, 1, O, z, nullptr, nullptr, 0);
    } else {
        mm_k<64><<<dim3(NP / 128, O / 64, BB), 256>>>(xin, xbs, C, W, ldw, 0, O, y, nullptr, nullptr, 0);
        mm_k<64><<<dim3(NP / 128, O / 64, BB), 256>>>(xin, xbs, C, W, ldw, 1, O, z, nullptr, nullptr, 0);
    }
    gathermax_k<<<dim3(O / 4, NP / 64, BB), 256>>>(y, z, idxp, g, bbp, O, xcOut, (size_t)512 * NP);
}

extern "C" void kernel_launch(void* const* d_in, const int* in_sizes, int n_in,
                              void* d_out, int out_size) {
    const float* x   = (const float*)d_in[0];
    const float* w1  = (const float*)d_in[1];
    const float* w2  = (const float*)d_in[2];
    const float* w3  = (const float*)d_in[3];
    const float* w4  = (const float*)d_in[4];
    const float* w5  = (const float*)d_in[5];
    const float* fw1 = (const float*)d_in[6];
    const float* fw2 = (const float*)d_in[7];
    const float* fw3 = (const float*)d_in[8];
    const float* g1 = (const float*)d_in[9],  *b1 = (const float*)d_in[10];
    const float* g2 = (const float*)d_in[11], *b2 = (const float*)d_in[12];
    const float* g3 = (const float*)d_in[13], *b3 = (const float*)d_in[14];
    const float* g4 = (const float*)d_in[15], *b4 = (const float*)d_in[16];
    const float* g5 = (const float*)d_in[17], *b5 = (const float*)d_in[18];
    const float* g6 = (const float*)d_in[19], *b6 = (const float*)d_in[20];
    const float* g7 = (const float*)d_in[21], *b7 = (const float*)d_in[22];

    float *xc, *y, *z, *sq, *dist, *hm, *h1, *h2;
    int* idxp;
    cudaGetSymbolAddress((void**)&xc,   g_xc);
    cudaGetSymbolAddress((void**)&y,    g_y);
    cudaGetSymbolAddress((void**)&z,    g_z);
    cudaGetSymbolAddress((void**)&sq,   g_sq);
    cudaGetSymbolAddress((void**)&dist, g_dist);
    cudaGetSymbolAddress((void**)&hm,   g_hm);
    cudaGetSymbolAddress((void**)&h1,   g_h1);
    cudaGetSymbolAddress((void**)&h2,   g_h2);
    cudaGetSymbolAddress((void**)&idxp, g_idx);

    zero_k<<<(BB * 1024 + 255) / 256, 256>>>(hm, BB * 1024);

    edge_conv_launch(x,                     (size_t)3 * NP,   3,   w1, 6,   64,  g1, b1,
                     xc + (size_t)0 * NP,   y, z, sq, dist, idxp);
    edge_conv_launch(xc,                    (size_t)512 * NP, 64,  w2, 128, 64,  g2, b2,
                     xc + (size_t)64 * NP,  y, z, sq, dist, idxp);
    edge_conv_launch(xc + (size_t)64 * NP,  (size_t)512 * NP, 64,  w3, 128, 128, g3, b3,
                     xc + (size_t)128 * NP, y, z, sq, dist, idxp);
    edge_conv_launch(xc + (size_t)128 * NP, (size_t)512 * NP, 128, w4, 256, 256, g4, b4,
                     xc + (size_t)256 * NP, y, z, sq, dist, idxp);

    // conv5 (1024x512) fused bn+relu+max_n via atomicMax epilogue
    mm_k<128><<<dim3(NP / 128, 1024 / 128, BB), 256>>>(xc, (size_t)512 * NP, 512, w5, 512, 0,
                                                       1024, hm, g5, b5, 1);

    fc_k<<<(BB * 512 + 255) / 256, 256>>>(hm, 1024, fw1, 512, g6, b6, h1, 1);
    fc_k<<<(BB * 256 + 255) / 256, 256>>>(h1, 512, fw2, 256, g7, b7, h2, 1);
    fc_k<<<(BB * 40 + 255) / 256, 256>>>(h2, 256, fw3, 40, nullptr, nullptr, (float*)d_out, 0);
}